// round 3
// baseline (speedup 1.0000x reference)
#include <cuda_runtime.h>

#define BB 64
#define SS 512
#define EE 128
#define TT 10
#define VV 100000
#define ROWS (BB*SS)

// scratch (static device globals: allocation-free)
__device__ float g_proj[VV * 16];   // vocab projection: [v][w*4+g]
__device__ float g_pre[ROWS * 16];  // per-row preactivation + bias + theta, [row][w*4+g]
__device__ float g_h[ROWS * 4];     // hidden states per (b,s), [row][w]

// ---------------------------------------------------------------------------
// Kernel A1: project the ENTIRE vocab through the 4 gate weight matrices.
// proj[v][w*4+g] = sum_k emb[v][k] * Wg[k*4+w].
// ---------------------------------------------------------------------------
__global__ void proj_kernel(const float* __restrict__ emb,
                            const float* __restrict__ Wf, const float* __restrict__ Wi,
                            const float* __restrict__ Wu, const float* __restrict__ Wo)
{
    __shared__ float sW[128 * 16];  // sW[k*16 + w*4 + g] = Wg[k*4+w]
    int tid = threadIdx.x;
    for (int idx = tid; idx < 128 * 16; idx += blockDim.x) {
        int k = idx >> 4;
        int w = (idx >> 2) & 3;
        int g = idx & 3;
        const float* Wg = (g == 0) ? Wf : (g == 1) ? Wi : (g == 2) ? Wu : Wo;
        sW[idx] = Wg[k * 4 + w];
    }
    __syncthreads();

    int t = blockIdx.x * blockDim.x + tid;   // [0, VV*16)
    int j = t & 15;
    int v = t >> 4;
    const float4* e4 = (const float4*)(emb + (size_t)v * EE);

    float a0 = 0.f, a1 = 0.f, a2 = 0.f, a3 = 0.f;
    #pragma unroll
    for (int k4 = 0; k4 < 32; k4++) {
        float4 e = e4[k4];
        int k = k4 * 4;
        a0 = fmaf(e.x, sW[(k + 0) * 16 + j], a0);
        a1 = fmaf(e.y, sW[(k + 1) * 16 + j], a1);
        a2 = fmaf(e.z, sW[(k + 2) * 16 + j], a2);
        a3 = fmaf(e.w, sW[(k + 3) * 16 + j], a3);
    }
    g_proj[t] = (a0 + a1) + (a2 + a3);
}

// ---------------------------------------------------------------------------
// Kernel A2: gather 64B per row from the (L2-resident) projection table and
// add bias + theta.
// ---------------------------------------------------------------------------
__global__ void gather_kernel(const int* __restrict__ x,
                              const float* __restrict__ bf, const float* __restrict__ thf,
                              const float* __restrict__ bi, const float* __restrict__ thi,
                              const float* __restrict__ bu, const float* __restrict__ thu,
                              const float* __restrict__ bo, const float* __restrict__ tho)
{
    __shared__ float sC[16];  // sC[w*4+g] = b_g[w] + th_g[w]
    int tid = threadIdx.x;
    if (tid < 16) {
        int w = tid >> 2, g = tid & 3;
        const float* bg  = (g == 0) ? bf  : (g == 1) ? bi  : (g == 2) ? bu  : bo;
        const float* thg = (g == 0) ? thf : (g == 1) ? thi : (g == 2) ? thu : tho;
        sC[tid] = bg[w] + thg[w];
    }
    __syncthreads();

    int rid = blockIdx.x * blockDim.x + tid;
    if (rid >= ROWS) return;
    int token = x[rid];
    const float4* src = (const float4*)g_proj + (size_t)token * 4;
    float4* dst = (float4*)g_pre + (size_t)rid * 4;
    #pragma unroll
    for (int q = 0; q < 4; q++) {
        float4 v = src[q];
        v.x += sC[q * 4 + 0];
        v.y += sC[q * 4 + 1];
        v.z += sC[q * 4 + 2];
        v.w += sC[q * 4 + 3];
        dst[q] = v;
    }
}

// ---------------------------------------------------------------------------
// Kernel B: serial LSTM recurrence, wire-parallel + 2-way chain interleave.
// Each thread handles wire w of TWO independent batch chains; their dependent
// chains interleave to hide shfl/MUFU/FMA latency on the single warp.
// QLayer (analytically collapsed): z_w = cos(a_w);
//   out_w: w=0 -> z1 z2 z3 ; w=1 -> z0 z1 ; w=2 -> z0 z1 z2 ; w=3 -> z0 z1 z2 z3
// Gate math with fused reciprocals:
//   c = (cx*B*G + (2-G)*A) / (A*B*G),  A=1+e^{-qf}, B=1+e^{-qi}, G=1+e^{-2qu}
//   h = (1-e^{-2c}) / ((1+e^{-qo})(1+e^{-2c}))
// ---------------------------------------------------------------------------
__global__ void __launch_bounds__(32, 1) rec_kernel(const float* __restrict__ Wf,
                                                    const float* __restrict__ Wi,
                                                    const float* __restrict__ Wu,
                                                    const float* __restrict__ Wo)
{
    const unsigned FULL = 0xffffffffu;
    int lane = threadIdx.x;
    int r = lane & 3;           // wire
    int grp = lane >> 2;        // group within warp (0..7)

    int b0 = blockIdx.x * 16 + grp;      // chain 0
    int b1 = b0 + 8;                     // chain 1

    // hidden-to-gate weights for this wire: Wh[g][h] = Wg[(128+h)*4 + r]
    const float* Ws[4] = {Wf, Wi, Wu, Wo};
    float Wh[4][4];
    #pragma unroll
    for (int g = 0; g < 4; g++)
        #pragma unroll
        for (int h = 0; h < 4; h++)
            Wh[g][h] = Ws[g][(128 + h) * 4 + r];

    // product masks for this wire's QLayer output
    const bool m0 = (r != 0);
    const bool m2 = (r != 1);
    const bool m3 = (r == 0) | (r == 3);

    const float4* pp0 = (const float4*)g_pre + (size_t)b0 * 2048 + r;
    const float4* pp1 = (const float4*)g_pre + (size_t)b1 * 2048 + r;
    float* ho0 = g_h + (size_t)b0 * 2048 + r;
    float* ho1 = g_h + (size_t)b1 * 2048 + r;

    float hv[2] = {0.f, 0.f};
    float cv[2] = {0.f, 0.f};

    // software prefetch, distance 2, both chains
    float4 pA0 = pp0[0], pA1 = pp0[4];
    float4 pB0 = pp1[0], pB1 = pp1[4];

    for (int s = 0; s < SS; s++) {
        float4 p[2];
        p[0] = pA0; pA0 = pA1;
        p[1] = pB0; pB0 = pB1;
        if (s + 2 < SS) {
            pA1 = pp0[4 * (s + 2)];
            pB1 = pp1[4 * (s + 2)];
        }

        // broadcast hidden state across the 4-lane group, both chains
        float hx[2][4];
        #pragma unroll
        for (int c = 0; c < 2; c++) {
            hx[c][0] = __shfl_sync(FULL, hv[c], 0, 4);
            hx[c][1] = __shfl_sync(FULL, hv[c], 1, 4);
            hx[c][2] = __shfl_sync(FULL, hv[c], 2, 4);
            hx[c][3] = __shfl_sync(FULL, hv[c], 3, 4);
        }

        // angles for all 4 gates at this wire, z = cos(angle)
        float z[2][4];
        #pragma unroll
        for (int c = 0; c < 2; c++) {
            float px = p[c].x, py = p[c].y, pz = p[c].z, pw = p[c].w;
            float a0 = fmaf(hx[c][1], Wh[0][1], fmaf(hx[c][0], Wh[0][0], px)) + fmaf(hx[c][3], Wh[0][3], hx[c][2] * Wh[0][2]);
            float a1 = fmaf(hx[c][1], Wh[1][1], fmaf(hx[c][0], Wh[1][0], py)) + fmaf(hx[c][3], Wh[1][3], hx[c][2] * Wh[1][2]);
            float a2 = fmaf(hx[c][1], Wh[2][1], fmaf(hx[c][0], Wh[2][0], pz)) + fmaf(hx[c][3], Wh[2][3], hx[c][2] * Wh[2][2]);
            float a3 = fmaf(hx[c][1], Wh[3][1], fmaf(hx[c][0], Wh[3][0], pw)) + fmaf(hx[c][3], Wh[3][3], hx[c][2] * Wh[3][2]);
            z[c][0] = __cosf(a0);
            z[c][1] = __cosf(a1);
            z[c][2] = __cosf(a2);
            z[c][3] = __cosf(a3);
        }

        // gather z across wires per gate and form masked products
        float q[2][4];
        #pragma unroll
        for (int c = 0; c < 2; c++) {
            #pragma unroll
            for (int g = 0; g < 4; g++) {
                float v0 = __shfl_sync(FULL, z[c][g], 0, 4);
                float v1 = __shfl_sync(FULL, z[c][g], 1, 4);
                float v2 = __shfl_sync(FULL, z[c][g], 2, 4);
                float v3 = __shfl_sync(FULL, z[c][g], 3, 4);
                float t0 = m0 ? v0 : 1.0f;
                float t2 = m2 ? v2 : 1.0f;
                float t3 = m3 ? v3 : 1.0f;
                q[c][g] = (t0 * v1) * (t2 * t3);
            }
        }

        // gates with fused reciprocals, both chains
        #pragma unroll
        for (int c = 0; c < 2; c++) {
            float ef = __expf(-q[c][0]);
            float ei = __expf(-q[c][1]);
            float eg = __expf(-2.0f * q[c][2]);
            float eo = __expf(-q[c][3]);

            float A = 1.0f + ef;
            float B = 1.0f + ei;
            float G = 1.0f + eg;
            float P = B * G;
            float D = A * P;
            float num = fmaf(cv[c], P, (2.0f - G) * A);
            float cn = __fdividef(num, D);

            float ec = __expf(-2.0f * cn);
            float hn = __fdividef(1.0f - ec, (1.0f + eo) * (1.0f + ec));

            cv[c] = cn;
            hv[c] = hn;
        }
        ho0[4 * s] = hv[0];
        ho1[4 * s] = hv[1];
    }
}

// ---------------------------------------------------------------------------
// Kernel C: logits [4 -> 10] + log_softmax. One thread per (b,s).
// Wt/bt staged in shared memory.
// ---------------------------------------------------------------------------
__global__ void out_kernel(const float* __restrict__ Wt, const float* __restrict__ bt,
                           float* __restrict__ out)
{
    __shared__ float sWt[4 * TT];
    __shared__ float sbt[TT];
    int tid = threadIdx.x;
    if (tid < 4 * TT) sWt[tid] = Wt[tid];
    if (tid < TT) sbt[tid] = bt[tid];
    __syncthreads();

    int row = blockIdx.x * blockDim.x + tid;
    if (row >= ROWS) return;
    float4 h = ((const float4*)g_h)[row];

    float lg[TT];
    #pragma unroll
    for (int t = 0; t < TT; t++) {
        float v = sbt[t];
        v = fmaf(h.x, sWt[0 * TT + t], v);
        v = fmaf(h.y, sWt[1 * TT + t], v);
        v = fmaf(h.z, sWt[2 * TT + t], v);
        v = fmaf(h.w, sWt[3 * TT + t], v);
        lg[t] = v;
    }
    float m = lg[0];
    #pragma unroll
    for (int t = 1; t < TT; t++) m = fmaxf(m, lg[t]);
    float sum = 0.f;
    #pragma unroll
    for (int t = 0; t < TT; t++) sum += __expf(lg[t] - m);
    float lse = m + __logf(sum);
    #pragma unroll
    for (int t = 0; t < TT; t++) out[row * TT + t] = lg[t] - lse;
}

// ---------------------------------------------------------------------------
extern "C" void kernel_launch(void* const* d_in, const int* in_sizes, int n_in,
                              void* d_out, int out_size)
{
    (void)in_sizes; (void)n_in; (void)out_size;
    const int*   x   = (const int*)  d_in[0];
    const float* emb = (const float*)d_in[1];
    const float* Wf  = (const float*)d_in[2];
    const float* bf  = (const float*)d_in[3];
    const float* thf = (const float*)d_in[4];
    const float* Wi  = (const float*)d_in[5];
    const float* bi  = (const float*)d_in[6];
    const float* thi = (const float*)d_in[7];
    const float* Wu  = (const float*)d_in[8];
    const float* bu  = (const float*)d_in[9];
    const float* thu = (const float*)d_in[10];
    const float* Wo  = (const float*)d_in[11];
    const float* bo  = (const float*)d_in[12];
    const float* tho = (const float*)d_in[13];
    const float* Wt  = (const float*)d_in[14];
    const float* bt  = (const float*)d_in[15];
    float* out = (float*)d_out;

    proj_kernel<<<(VV * 16) / 256, 256>>>(emb, Wf, Wi, Wu, Wo);
    gather_kernel<<<ROWS / 256, 256>>>(x, bf, thf, bi, thi, bu, thu, bo, tho);
    rec_kernel<<<4, 32>>>(Wf, Wi, Wu, Wo);
    out_kernel<<<ROWS / 256, 256>>>(Wt, bt, out);
}

// round 4
// speedup vs baseline: 1.1807x; 1.1807x over previous
#include <cuda_runtime.h>

#define BB 64
#define SS 512
#define EE 128
#define TT 10
#define VV 100000
#define ROWS (BB*SS)

// scratch (static device globals: allocation-free)
__device__ float g_proj[VV * 16];   // vocab projection + bias + theta: [v][g*4+w]
__device__ float g_pre[ROWS * 16];  // per-row preactivation: [row][g*4+w]
__device__ float g_h[ROWS * 4];     // hidden states per (b,s), [row][w]

// ---------------------------------------------------------------------------
// Kernel A1: project the ENTIRE vocab through the 4 gate weight matrices and
// fold in bias + theta.  proj[v][g*4+w] = sum_k emb[v][k]*Wg[k*4+w] + bg[w]+thg[w]
// ---------------------------------------------------------------------------
__global__ void proj_kernel(const float* __restrict__ emb,
                            const float* __restrict__ Wf, const float* __restrict__ bf, const float* __restrict__ thf,
                            const float* __restrict__ Wi, const float* __restrict__ bi, const float* __restrict__ thi,
                            const float* __restrict__ Wu, const float* __restrict__ bu, const float* __restrict__ thu,
                            const float* __restrict__ Wo, const float* __restrict__ bo, const float* __restrict__ tho)
{
    __shared__ float sW[128 * 16];  // sW[k*16 + g*4 + w] = Wg[k*4+w]
    __shared__ float sC[16];        // sC[g*4+w] = bg[w] + thg[w]
    int tid = threadIdx.x;
    for (int idx = tid; idx < 128 * 16; idx += blockDim.x) {
        int k = idx >> 4;
        int g = (idx >> 2) & 3;
        int w = idx & 3;
        const float* Wg = (g == 0) ? Wf : (g == 1) ? Wi : (g == 2) ? Wu : Wo;
        sW[idx] = Wg[k * 4 + w];
    }
    if (tid < 16) {
        int g = tid >> 2, w = tid & 3;
        const float* bg  = (g == 0) ? bf  : (g == 1) ? bi  : (g == 2) ? bu  : bo;
        const float* thg = (g == 0) ? thf : (g == 1) ? thi : (g == 2) ? thu : tho;
        sC[tid] = bg[w] + thg[w];
    }
    __syncthreads();

    int t = blockIdx.x * blockDim.x + tid;   // [0, VV*16)
    int j = t & 15;
    int v = t >> 4;
    const float4* e4 = (const float4*)(emb + (size_t)v * EE);

    float a0 = 0.f, a1 = 0.f, a2 = 0.f, a3 = 0.f;
    #pragma unroll
    for (int k4 = 0; k4 < 32; k4++) {
        float4 e = e4[k4];
        int k = k4 * 4;
        a0 = fmaf(e.x, sW[(k + 0) * 16 + j], a0);
        a1 = fmaf(e.y, sW[(k + 1) * 16 + j], a1);
        a2 = fmaf(e.z, sW[(k + 2) * 16 + j], a2);
        a3 = fmaf(e.w, sW[(k + 3) * 16 + j], a3);
    }
    g_proj[t] = (a0 + a1) + (a2 + a3) + sC[j];
}

// ---------------------------------------------------------------------------
// Kernel A2: pure gather: copy 64B per row from the L2-resident projection.
// ---------------------------------------------------------------------------
__global__ void gather_kernel(const int* __restrict__ x)
{
    int rid = blockIdx.x * blockDim.x + threadIdx.x;
    if (rid >= ROWS) return;
    int token = x[rid];
    const float4* src = (const float4*)g_proj + (size_t)token * 4;
    float4* dst = (float4*)g_pre + (size_t)rid * 4;
    #pragma unroll
    for (int q = 0; q < 4; q++) dst[q] = src[q];
}

// ---------------------------------------------------------------------------
// Kernel B: serial LSTM recurrence, 16 lanes per chain (lane = g*4 + w),
// 2 chains per warp (width-16 shuffle segments), 32 warps total.
//
// Per step: each lane computes its ONE angle a[g][w] = p + Wh_col . h,
// z = cos(a); 4-shfl gather of z within the gate group -> masked product q;
// e = exp(scale * q) per lane; 3 shfls bring e_i, e_u, e_o to the f-lanes,
// which carry cx and compute (fused reciprocals):
//   c = (cx*B*G + A*(1-eu)) / (A*B*G),  A=1+ef, B=1+ei, G=1+eu'
//   h = (1-ec) / ((1+eo)*(1+ec)),  ec = exp(-2c)
// h lives on f-lanes (w = 0..3), broadcast at top of next step.
// ---------------------------------------------------------------------------
__global__ void __launch_bounds__(32, 1) rec_kernel(const float* __restrict__ Wf,
                                                    const float* __restrict__ Wi,
                                                    const float* __restrict__ Wu,
                                                    const float* __restrict__ Wo)
{
    const unsigned FULL = 0xffffffffu;
    int lane  = threadIdx.x;
    int chain = lane >> 4;        // 0/1 within warp
    int sub   = lane & 15;        // position within chain segment
    int g     = sub >> 2;         // gate: 0=f 1=i 2=u 3=o
    int w     = sub & 3;          // wire
    int b     = blockIdx.x * 2 + chain;

    // this lane's 4 hidden-to-gate weights: Wh[h] = Wg[(128+h)*4 + w]
    const float* Wg = (g == 0) ? Wf : (g == 1) ? Wi : (g == 2) ? Wu : Wo;
    float Wh0 = Wg[(128 + 0) * 4 + w];
    float Wh1 = Wg[(128 + 1) * 4 + w];
    float Wh2 = Wg[(128 + 2) * 4 + w];
    float Wh3 = Wg[(128 + 3) * 4 + w];

    // masked-product selectors for this wire's QLayer output
    const bool m0 = (w != 0);
    const bool m2 = (w == 0) | (w >= 2);
    const bool m3 = (w == 0) | (w == 3);
    // gate exp scale: u-gate (tanh) uses exp(-2q), sigmoids use exp(-q)
    const float esc = (g == 2) ? -2.0f : -1.0f;

    // z-gather source lanes (within gate group) and e-shfl sources
    const int gbase = sub & 12;

    const float* P = g_pre + (size_t)b * SS * 16 + sub;  // stride 16 floats/step
    float* hout = g_h + (size_t)b * SS * 4 + w;          // f-lanes store

    float hv = 0.f, cx = 0.f;

    // software prefetch, distance 2
    float p0 = P[0];
    float p1 = P[16];

    for (int s = 0; s < SS; s++) {
        float p = p0;
        p0 = p1;
        if (s + 2 < SS) p1 = P[16 * (s + 2)];

        // broadcast hidden state (lives on f-lanes 0..3 of each segment)
        float hx0 = __shfl_sync(FULL, hv, 0, 16);
        float hx1 = __shfl_sync(FULL, hv, 1, 16);
        float hx2 = __shfl_sync(FULL, hv, 2, 16);
        float hx3 = __shfl_sync(FULL, hv, 3, 16);

        // this lane's angle and z
        float a = fmaf(hx1, Wh1, fmaf(hx0, Wh0, p)) + fmaf(hx3, Wh3, hx2 * Wh2);
        float z = __cosf(a);

        // gather z across the 4 wires of this gate group (independent shfls)
        float z0 = __shfl_sync(FULL, z, gbase | 0, 16);
        float z1 = __shfl_sync(FULL, z, gbase | 1, 16);
        float z2 = __shfl_sync(FULL, z, gbase | 2, 16);
        float z3 = __shfl_sync(FULL, z, gbase | 3, 16);

        // masked product = QLayer output for (gate g, wire w)
        float t01 = (m0 ? z0 : 1.0f) * z1;
        float t23 = (m2 ? z2 : 1.0f) * (m3 ? z3 : 1.0f);
        float q = t01 * t23;

        // gate exponential (per lane)
        float e = __expf(esc * q);

        // bring i, u, o exponentials to the f-lanes (independent shfls)
        float ei = __shfl_sync(FULL, e, 4  | w, 16);
        float eu = __shfl_sync(FULL, e, 8  | w, 16);
        float eo = __shfl_sync(FULL, e, 12 | w, 16);

        // cell update with fused reciprocals (meaningful on f-lanes only)
        float A = 1.0f + e;       // 1 + ef on f-lanes
        float B = 1.0f + ei;
        float G = 1.0f + eu;
        float BG = B * G;
        float num = fmaf(cx, BG, A * (1.0f - eu));
        float c = __fdividef(num, A * BG);

        float ec = __expf(-2.0f * c);
        float Ko = 1.0f + eo;      // off critical path (ready before c)
        float hn = __fdividef(1.0f - ec, Ko * (1.0f + ec));

        cx = c;
        hv = hn;
        if (g == 0) hout[4 * s] = hn;
    }
}

// ---------------------------------------------------------------------------
// Kernel C: logits [4 -> 10] + log_softmax. One thread per (b,s).
// ---------------------------------------------------------------------------
__global__ void out_kernel(const float* __restrict__ Wt, const float* __restrict__ bt,
                           float* __restrict__ out)
{
    __shared__ float sWt[4 * TT];
    __shared__ float sbt[TT];
    int tid = threadIdx.x;
    if (tid < 4 * TT) sWt[tid] = Wt[tid];
    if (tid < TT) sbt[tid] = bt[tid];
    __syncthreads();

    int row = blockIdx.x * blockDim.x + tid;
    if (row >= ROWS) return;
    float4 h = ((const float4*)g_h)[row];

    float lg[TT];
    #pragma unroll
    for (int t = 0; t < TT; t++) {
        float v = sbt[t];
        v = fmaf(h.x, sWt[0 * TT + t], v);
        v = fmaf(h.y, sWt[1 * TT + t], v);
        v = fmaf(h.z, sWt[2 * TT + t], v);
        v = fmaf(h.w, sWt[3 * TT + t], v);
        lg[t] = v;
    }
    float m = lg[0];
    #pragma unroll
    for (int t = 1; t < TT; t++) m = fmaxf(m, lg[t]);
    float sum = 0.f;
    #pragma unroll
    for (int t = 0; t < TT; t++) sum += __expf(lg[t] - m);
    float lse = m + __logf(sum);
    #pragma unroll
    for (int t = 0; t < TT; t++) out[row * TT + t] = lg[t] - lse;
}

// ---------------------------------------------------------------------------
extern "C" void kernel_launch(void* const* d_in, const int* in_sizes, int n_in,
                              void* d_out, int out_size)
{
    (void)in_sizes; (void)n_in; (void)out_size;
    const int*   x   = (const int*)  d_in[0];
    const float* emb = (const float*)d_in[1];
    const float* Wf  = (const float*)d_in[2];
    const float* bf  = (const float*)d_in[3];
    const float* thf = (const float*)d_in[4];
    const float* Wi  = (const float*)d_in[5];
    const float* bi  = (const float*)d_in[6];
    const float* thi = (const float*)d_in[7];
    const float* Wu  = (const float*)d_in[8];
    const float* bu  = (const float*)d_in[9];
    const float* thu = (const float*)d_in[10];
    const float* Wo  = (const float*)d_in[11];
    const float* bo  = (const float*)d_in[12];
    const float* tho = (const float*)d_in[13];
    const float* Wt  = (const float*)d_in[14];
    const float* bt  = (const float*)d_in[15];
    float* out = (float*)d_out;

    proj_kernel<<<(VV * 16) / 256, 256>>>(emb, Wf, bf, thf, Wi, bi, thi,
                                          Wu, bu, thu, Wo, bo, tho);
    gather_kernel<<<ROWS / 256, 256>>>(x);
    rec_kernel<<<32, 32>>>(Wf, Wi, Wu, Wo);
    out_kernel<<<ROWS / 256, 256>>>(Wt, bt, out);
}

// round 5
// speedup vs baseline: 1.6663x; 1.4113x over previous
#include <cuda_runtime.h>

#define BB 64
#define SS 512
#define EE 128
#define TT 10
#define VV 100000
#define ROWS (BB*SS)

// scratch (static device globals: allocation-free)
__device__ float g_proj[VV * 16];          // vocab projection + bias + theta: [v][g*4+w]
__device__ float g_pre[ROWS * 16 + 64];    // per-row preactivation (+ pad for branchless prefetch)
__device__ float g_h[ROWS * 4];            // hidden states per (b,s), [row][w]

__device__ __forceinline__ float tanh_approx(float x) {
    float y;
    asm("tanh.approx.f32 %0, %1;" : "=f"(y) : "f"(x));
    return y;
}

// ---------------------------------------------------------------------------
// Kernel A1: project the ENTIRE vocab through the 4 gate weight matrices and
// fold in bias + theta.  proj[v][g*4+w] = sum_k emb[v][k]*Wg[k*4+w] + bg[w]+thg[w]
// ---------------------------------------------------------------------------
__global__ void proj_kernel(const float* __restrict__ emb,
                            const float* __restrict__ Wf, const float* __restrict__ bf, const float* __restrict__ thf,
                            const float* __restrict__ Wi, const float* __restrict__ bi, const float* __restrict__ thi,
                            const float* __restrict__ Wu, const float* __restrict__ bu, const float* __restrict__ thu,
                            const float* __restrict__ Wo, const float* __restrict__ bo, const float* __restrict__ tho)
{
    __shared__ float sW[128 * 16];  // sW[k*16 + g*4 + w] = Wg[k*4+w]
    __shared__ float sC[16];        // sC[g*4+w] = bg[w] + thg[w]
    int tid = threadIdx.x;
    for (int idx = tid; idx < 128 * 16; idx += blockDim.x) {
        int k = idx >> 4;
        int g = (idx >> 2) & 3;
        int w = idx & 3;
        const float* Wg = (g == 0) ? Wf : (g == 1) ? Wi : (g == 2) ? Wu : Wo;
        sW[idx] = Wg[k * 4 + w];
    }
    if (tid < 16) {
        int g = tid >> 2, w = tid & 3;
        const float* bg  = (g == 0) ? bf  : (g == 1) ? bi  : (g == 2) ? bu  : bo;
        const float* thg = (g == 0) ? thf : (g == 1) ? thi : (g == 2) ? thu : tho;
        sC[tid] = bg[w] + thg[w];
    }
    __syncthreads();

    int t = blockIdx.x * blockDim.x + tid;   // [0, VV*16)
    int j = t & 15;
    int v = t >> 4;
    const float4* e4 = (const float4*)(emb + (size_t)v * EE);

    float a0 = 0.f, a1 = 0.f, a2 = 0.f, a3 = 0.f;
    #pragma unroll
    for (int k4 = 0; k4 < 32; k4++) {
        float4 e = e4[k4];
        int k = k4 * 4;
        a0 = fmaf(e.x, sW[(k + 0) * 16 + j], a0);
        a1 = fmaf(e.y, sW[(k + 1) * 16 + j], a1);
        a2 = fmaf(e.z, sW[(k + 2) * 16 + j], a2);
        a3 = fmaf(e.w, sW[(k + 3) * 16 + j], a3);
    }
    g_proj[t] = (a0 + a1) + (a2 + a3) + sC[j];
}

// ---------------------------------------------------------------------------
// Kernel A2: pure gather: copy 64B per row from the L2-resident projection.
// ---------------------------------------------------------------------------
__global__ void gather_kernel(const int* __restrict__ x)
{
    int rid = blockIdx.x * blockDim.x + threadIdx.x;
    if (rid >= ROWS) return;
    int token = x[rid];
    const float4* src = (const float4*)g_proj + (size_t)token * 4;
    float4* dst = (float4*)g_pre + (size_t)rid * 4;
    #pragma unroll
    for (int q = 0; q < 4; q++) dst[q] = src[q];
}

// ---------------------------------------------------------------------------
// Kernel B: serial LSTM recurrence, 16 lanes per chain (lane = g*4 + w),
// 2 chains per warp, 32 warps. Critical path minimized with MUFU.TANH:
//   sigmoid(x) = 0.5*tanh(x/2)+0.5 ; g = tanh(q) ; h = o*tanh(c)
// Loop unrolled x4, branchless prefetch via padded g_pre.
// ---------------------------------------------------------------------------
__global__ void __launch_bounds__(32, 1) rec_kernel(const float* __restrict__ Wf,
                                                    const float* __restrict__ Wi,
                                                    const float* __restrict__ Wu,
                                                    const float* __restrict__ Wo)
{
    const unsigned FULL = 0xffffffffu;
    int lane  = threadIdx.x;
    int sub   = lane & 15;        // position within chain segment
    int g     = sub >> 2;         // gate: 0=f 1=i 2=u 3=o
    int w     = sub & 3;          // wire
    int b     = blockIdx.x * 2 + (lane >> 4);

    // this lane's 4 hidden-to-gate weights
    const float* Wg = (g == 0) ? Wf : (g == 1) ? Wi : (g == 2) ? Wu : Wo;
    float Wh0 = Wg[(128 + 0) * 4 + w];
    float Wh1 = Wg[(128 + 1) * 4 + w];
    float Wh2 = Wg[(128 + 2) * 4 + w];
    float Wh3 = Wg[(128 + 3) * 4 + w];

    // masked-product selectors for this wire's QLayer output
    const bool m0 = (w != 0);
    const bool m2 = (w == 0) | (w >= 2);
    const bool m3 = (w == 0) | (w == 3);
    // tanh arg scale: u-gate = tanh(q) -> 1.0 ; sigmoids = tanh(q/2) -> 0.5
    const float tsc = (g == 2) ? 1.0f : 0.5f;

    const int gbase = sub & 12;

    const float* P = g_pre + (size_t)b * SS * 16 + sub;  // stride 16 floats/step
    float* hout = g_h + (size_t)b * SS * 4 + w;          // f-lanes store

    float hv = 0.f, cx = 0.f;

    // prefetch buffers: current 4 steps + next 4 steps
    float pc0, pc1, pc2, pc3;
    float pb0 = P[0 * 16], pb1 = P[1 * 16], pb2 = P[2 * 16], pb3 = P[3 * 16];

    for (int sb = 0; sb < SS; sb += 4) {
        pc0 = pb0; pc1 = pb1; pc2 = pb2; pc3 = pb3;
        // branchless prefetch of the next block (padded array)
        pb0 = P[4 * 16]; pb1 = P[5 * 16]; pb2 = P[6 * 16]; pb3 = P[7 * 16];
        P += 64;

        #pragma unroll
        for (int k = 0; k < 4; k++) {
            float p = (k == 0) ? pc0 : (k == 1) ? pc1 : (k == 2) ? pc2 : pc3;

            // broadcast hidden state (lives on f-lanes 0..3 of each segment)
            float hx0 = __shfl_sync(FULL, hv, 0, 16);
            float hx1 = __shfl_sync(FULL, hv, 1, 16);
            float hx2 = __shfl_sync(FULL, hv, 2, 16);
            float hx3 = __shfl_sync(FULL, hv, 3, 16);

            // this lane's angle and z
            float a = fmaf(hx1, Wh1, fmaf(hx0, Wh0, p)) + fmaf(hx3, Wh3, hx2 * Wh2);
            float z = __cosf(a);

            // gather z across the 4 wires of this gate group
            float z0 = __shfl_sync(FULL, z, gbase | 0, 16);
            float z1 = __shfl_sync(FULL, z, gbase | 1, 16);
            float z2 = __shfl_sync(FULL, z, gbase | 2, 16);
            float z3 = __shfl_sync(FULL, z, gbase | 3, 16);

            // masked product = QLayer output for (gate g, wire w)
            float t01 = (m0 ? z0 : 1.0f) * z1;
            float t23 = (m2 ? z2 : 1.0f) * (m3 ? z3 : 1.0f);
            float q = t01 * t23;

            // gate nonlinearity via MUFU.TANH
            float t = tanh_approx(q * tsc);

            // bring i, u, o tanh values to the f-lanes
            float ti = __shfl_sync(FULL, t, 4  | w, 16);
            float tu = __shfl_sync(FULL, t, 8  | w, 16);
            float to = __shfl_sync(FULL, t, 12 | w, 16);

            // cell + hidden update (meaningful on f-lanes only)
            float fv = fmaf(t,  0.5f, 0.5f);
            float iv = fmaf(ti, 0.5f, 0.5f);
            float ov = fmaf(to, 0.5f, 0.5f);
            float c  = fmaf(fv, cx, iv * tu);
            float hn = ov * tanh_approx(c);

            cx = c;
            hv = hn;
            if (g == 0) hout[4 * k] = hn;
        }
        hout += 16;
    }
}

// ---------------------------------------------------------------------------
// Kernel C: logits [4 -> 10] + log_softmax. One thread per (b,s).
// ---------------------------------------------------------------------------
__global__ void out_kernel(const float* __restrict__ Wt, const float* __restrict__ bt,
                           float* __restrict__ out)
{
    __shared__ float sWt[4 * TT];
    __shared__ float sbt[TT];
    int tid = threadIdx.x;
    if (tid < 4 * TT) sWt[tid] = Wt[tid];
    if (tid < TT) sbt[tid] = bt[tid];
    __syncthreads();

    int row = blockIdx.x * blockDim.x + tid;
    if (row >= ROWS) return;
    float4 h = ((const float4*)g_h)[row];

    float lg[TT];
    #pragma unroll
    for (int t = 0; t < TT; t++) {
        float v = sbt[t];
        v = fmaf(h.x, sWt[0 * TT + t], v);
        v = fmaf(h.y, sWt[1 * TT + t], v);
        v = fmaf(h.z, sWt[2 * TT + t], v);
        v = fmaf(h.w, sWt[3 * TT + t], v);
        lg[t] = v;
    }
    float m = lg[0];
    #pragma unroll
    for (int t = 1; t < TT; t++) m = fmaxf(m, lg[t]);
    float sum = 0.f;
    #pragma unroll
    for (int t = 0; t < TT; t++) sum += __expf(lg[t] - m);
    float lse = m + __logf(sum);

    float2* o2 = (float2*)(out + (size_t)row * TT);
    #pragma unroll
    for (int t = 0; t < TT; t += 2)
        o2[t >> 1] = make_float2(lg[t] - lse, lg[t + 1] - lse);
}

// ---------------------------------------------------------------------------
extern "C" void kernel_launch(void* const* d_in, const int* in_sizes, int n_in,
                              void* d_out, int out_size)
{
    (void)in_sizes; (void)n_in; (void)out_size;
    const int*   x   = (const int*)  d_in[0];
    const float* emb = (const float*)d_in[1];
    const float* Wf  = (const float*)d_in[2];
    const float* bf  = (const float*)d_in[3];
    const float* thf = (const float*)d_in[4];
    const float* Wi  = (const float*)d_in[5];
    const float* bi  = (const float*)d_in[6];
    const float* thi = (const float*)d_in[7];
    const float* Wu  = (const float*)d_in[8];
    const float* bu  = (const float*)d_in[9];
    const float* thu = (const float*)d_in[10];
    const float* Wo  = (const float*)d_in[11];
    const float* bo  = (const float*)d_in[12];
    const float* tho = (const float*)d_in[13];
    const float* Wt  = (const float*)d_in[14];
    const float* bt  = (const float*)d_in[15];
    float* out = (float*)d_out;

    proj_kernel<<<(VV * 16) / 256, 256>>>(emb, Wf, bf, thf, Wi, bi, thi,
                                          Wu, bu, thu, Wo, bo, tho);
    gather_kernel<<<ROWS / 256, 256>>>(x);
    rec_kernel<<<32, 32>>>(Wf, Wi, Wu, Wo);
    out_kernel<<<256, 128>>>(Wt, bt, out);
}

// round 6
// speedup vs baseline: 1.8055x; 1.0835x over previous
#include <cuda_runtime.h>

#define BB 64
#define SS 512
#define EE 128
#define TT 10
#define VV 100000
#define ROWS (BB*SS)

// scratch (static device globals: allocation-free)
__device__ float g_proj[VV * 16];   // vocab projection + bias + theta: [v][g*4+w]
__device__ float g_h[ROWS * 4];     // hidden states per (b,s), [row][w]

__device__ __forceinline__ float tanh_approx(float x) {
    float y;
    asm("tanh.approx.f32 %0, %1;" : "=f"(y) : "f"(x));
    return y;
}

// ---------------------------------------------------------------------------
// Kernel A: project the ENTIRE vocab through the 4 gate weight matrices and
// fold in bias + theta.  proj[v][g*4+w] = sum_k emb[v][k]*Wg[k*4+w] + bg[w]+thg[w]
// ---------------------------------------------------------------------------
__global__ void proj_kernel(const float* __restrict__ emb,
                            const float* __restrict__ Wf, const float* __restrict__ bf, const float* __restrict__ thf,
                            const float* __restrict__ Wi, const float* __restrict__ bi, const float* __restrict__ thi,
                            const float* __restrict__ Wu, const float* __restrict__ bu, const float* __restrict__ thu,
                            const float* __restrict__ Wo, const float* __restrict__ bo, const float* __restrict__ tho)
{
    __shared__ float sW[128 * 16];  // sW[k*16 + g*4 + w] = Wg[k*4+w]
    __shared__ float sC[16];        // sC[g*4+w] = bg[w] + thg[w]
    int tid = threadIdx.x;
    for (int idx = tid; idx < 128 * 16; idx += blockDim.x) {
        int k = idx >> 4;
        int g = (idx >> 2) & 3;
        int w = idx & 3;
        const float* Wg = (g == 0) ? Wf : (g == 1) ? Wi : (g == 2) ? Wu : Wo;
        sW[idx] = Wg[k * 4 + w];
    }
    if (tid < 16) {
        int g = tid >> 2, w = tid & 3;
        const float* bg  = (g == 0) ? bf  : (g == 1) ? bi  : (g == 2) ? bu  : bo;
        const float* thg = (g == 0) ? thf : (g == 1) ? thi : (g == 2) ? thu : tho;
        sC[tid] = bg[w] + thg[w];
    }
    __syncthreads();

    int t = blockIdx.x * blockDim.x + tid;   // [0, VV*16)
    int j = t & 15;
    int v = t >> 4;
    const float4* e4 = (const float4*)(emb + (size_t)v * EE);

    float a0 = 0.f, a1 = 0.f, a2 = 0.f, a3 = 0.f;
    #pragma unroll
    for (int k4 = 0; k4 < 32; k4++) {
        float4 e = e4[k4];
        int k = k4 * 4;
        a0 = fmaf(e.x, sW[(k + 0) * 16 + j], a0);
        a1 = fmaf(e.y, sW[(k + 1) * 16 + j], a1);
        a2 = fmaf(e.z, sW[(k + 2) * 16 + j], a2);
        a3 = fmaf(e.w, sW[(k + 3) * 16 + j], a3);
    }
    g_proj[t] = (a0 + a1) + (a2 + a3) + sC[j];
}

// ---------------------------------------------------------------------------
// Kernel B: serial LSTM recurrence. ONE chain per warp (lanes 0-15 active,
// lane = g*4 + w), 64 warps on 64 SMs -> minimal per-warp shfl/MUFU issue.
// Reads g_proj DIRECTLY via token indices, prefetched 4-8 steps ahead
// (g_proj is L2-resident after proj_kernel).
//   sigmoid(x) = 0.5*tanh(x/2)+0.5 ; g = tanh(q) ; h = o*tanh(c)
// ---------------------------------------------------------------------------
__global__ void __launch_bounds__(32, 1) rec_kernel(const int* __restrict__ x,
                                                    const float* __restrict__ Wf,
                                                    const float* __restrict__ Wi,
                                                    const float* __restrict__ Wu,
                                                    const float* __restrict__ Wo)
{
    const unsigned FULL = 0xffffffffu;
    int lane = threadIdx.x;
    int sub  = lane & 15;         // lane role (lanes 16-31 mirror 0-15, results unused)
    int g    = sub >> 2;          // gate: 0=f 1=i 2=u 3=o
    int w    = sub & 3;           // wire
    int b    = blockIdx.x;

    // this lane's 4 hidden-to-gate weights
    const float* Wg = (g == 0) ? Wf : (g == 1) ? Wi : (g == 2) ? Wu : Wo;
    float Wh0 = Wg[(128 + 0) * 4 + w];
    float Wh1 = Wg[(128 + 1) * 4 + w];
    float Wh2 = Wg[(128 + 2) * 4 + w];
    float Wh3 = Wg[(128 + 3) * 4 + w];

    // masked-product selectors for this wire's QLayer output
    const bool m0 = (w != 0);
    const bool m2 = (w == 0) | (w >= 2);
    const bool m3 = (w == 0) | (w == 3);
    // tanh arg scale: u-gate = tanh(q) ; sigmoids = tanh(q/2)
    const float tsc = (g == 2) ? 1.0f : 0.5f;
    const int gbase = sub & 12;

    const int4* X4 = (const int4*)(x + (size_t)b * SS);   // 128 blocks of 4 tokens
    const float* PJ = g_proj + sub;                        // + token*16
    float* hout = g_h + (size_t)b * SS * 4 + w;            // f-lanes store

    float hv = 0.f, cx = 0.f;

    // token / preactivation prefetch pipeline (distance: 1 block = 4 steps)
    int4 t4 = X4[0];
    float pn0 = PJ[(size_t)t4.x * 16];
    float pn1 = PJ[(size_t)t4.y * 16];
    float pn2 = PJ[(size_t)t4.z * 16];
    float pn3 = PJ[(size_t)t4.w * 16];
    t4 = X4[1];

    for (int blk = 0; blk < 128; blk++) {
        float pc0 = pn0, pc1 = pn1, pc2 = pn2, pc3 = pn3;
        // issue loads for next block (tokens already in regs); last iter loads
        // block-0 tokens again (valid addresses, values unused)
        pn0 = PJ[(size_t)t4.x * 16];
        pn1 = PJ[(size_t)t4.y * 16];
        pn2 = PJ[(size_t)t4.z * 16];
        pn3 = PJ[(size_t)t4.w * 16];
        int nb = blk + 2;
        t4 = X4[nb < 128 ? nb : 0];

        #pragma unroll
        for (int k = 0; k < 4; k++) {
            float p = (k == 0) ? pc0 : (k == 1) ? pc1 : (k == 2) ? pc2 : pc3;

            // broadcast hidden state (lives on f-lanes 0..3 of each segment)
            float hx0 = __shfl_sync(FULL, hv, 0, 16);
            float hx1 = __shfl_sync(FULL, hv, 1, 16);
            float hx2 = __shfl_sync(FULL, hv, 2, 16);
            float hx3 = __shfl_sync(FULL, hv, 3, 16);

            // this lane's angle and z
            float a = fmaf(hx1, Wh1, fmaf(hx0, Wh0, p)) + fmaf(hx3, Wh3, hx2 * Wh2);
            float z = __cosf(a);

            // gather z across the 4 wires of this gate group
            float z0 = __shfl_sync(FULL, z, gbase | 0, 16);
            float z1 = __shfl_sync(FULL, z, gbase | 1, 16);
            float z2 = __shfl_sync(FULL, z, gbase | 2, 16);
            float z3 = __shfl_sync(FULL, z, gbase | 3, 16);

            // masked product = QLayer output for (gate g, wire w)
            float t01 = (m0 ? z0 : 1.0f) * z1;
            float t23 = (m2 ? z2 : 1.0f) * (m3 ? z3 : 1.0f);
            float q = t01 * t23;

            // gate nonlinearity via MUFU.TANH
            float t = tanh_approx(q * tsc);

            // bring i, u, o tanh values to the f-lanes
            float ti = __shfl_sync(FULL, t, 4  | w, 16);
            float tu = __shfl_sync(FULL, t, 8  | w, 16);
            float to = __shfl_sync(FULL, t, 12 | w, 16);

            // cell + hidden update (meaningful on f-lanes only)
            float fv = fmaf(t,  0.5f, 0.5f);
            float iv = fmaf(ti, 0.5f, 0.5f);
            float ov = fmaf(to, 0.5f, 0.5f);
            float c  = fmaf(fv, cx, iv * tu);
            float hn = ov * tanh_approx(c);

            cx = c;
            hv = hn;
            if (g == 0 && lane < 16) hout[4 * k] = hn;
        }
        hout += 16;
    }
}

// ---------------------------------------------------------------------------
// Kernel C: logits [4 -> 10] + log_softmax. One thread per (b,s).
// ---------------------------------------------------------------------------
__global__ void out_kernel(const float* __restrict__ Wt, const float* __restrict__ bt,
                           float* __restrict__ out)
{
    __shared__ float sWt[4 * TT];
    __shared__ float sbt[TT];
    int tid = threadIdx.x;
    if (tid < 4 * TT) sWt[tid] = Wt[tid];
    if (tid < TT) sbt[tid] = bt[tid];
    __syncthreads();

    int row = blockIdx.x * blockDim.x + tid;
    if (row >= ROWS) return;
    float4 h = ((const float4*)g_h)[row];

    float lg[TT];
    #pragma unroll
    for (int t = 0; t < TT; t++) {
        float v = sbt[t];
        v = fmaf(h.x, sWt[0 * TT + t], v);
        v = fmaf(h.y, sWt[1 * TT + t], v);
        v = fmaf(h.z, sWt[2 * TT + t], v);
        v = fmaf(h.w, sWt[3 * TT + t], v);
        lg[t] = v;
    }
    float m = lg[0];
    #pragma unroll
    for (int t = 1; t < TT; t++) m = fmaxf(m, lg[t]);
    float sum = 0.f;
    #pragma unroll
    for (int t = 0; t < TT; t++) sum += __expf(lg[t] - m);
    float lse = m + __logf(sum);

    float2* o2 = (float2*)(out + (size_t)row * TT);
    #pragma unroll
    for (int t = 0; t < TT; t += 2)
        o2[t >> 1] = make_float2(lg[t] - lse, lg[t + 1] - lse);
}

// ---------------------------------------------------------------------------
extern "C" void kernel_launch(void* const* d_in, const int* in_sizes, int n_in,
                              void* d_out, int out_size)
{
    (void)in_sizes; (void)n_in; (void)out_size;
    const int*   x   = (const int*)  d_in[0];
    const float* emb = (const float*)d_in[1];
    const float* Wf  = (const float*)d_in[2];
    const float* bf  = (const float*)d_in[3];
    const float* thf = (const float*)d_in[4];
    const float* Wi  = (const float*)d_in[5];
    const float* bi  = (const float*)d_in[6];
    const float* thi = (const float*)d_in[7];
    const float* Wu  = (const float*)d_in[8];
    const float* bu  = (const float*)d_in[9];
    const float* thu = (const float*)d_in[10];
    const float* Wo  = (const float*)d_in[11];
    const float* bo  = (const float*)d_in[12];
    const float* tho = (const float*)d_in[13];
    const float* Wt  = (const float*)d_in[14];
    const float* bt  = (const float*)d_in[15];
    float* out = (float*)d_out;

    proj_kernel<<<(VV * 16) / 256, 256>>>(emb, Wf, bf, thf, Wi, bi, thi,
                                          Wu, bu, thu, Wo, bo, tho);
    rec_kernel<<<64, 32>>>(x, Wf, Wi, Wu, Wo);
    out_kernel<<<256, 128>>>(Wt, bt, out);
}

// round 7
// speedup vs baseline: 2.6878x; 1.4887x over previous
#include <cuda_runtime.h>

#define BB 64
#define SS 512
#define EE 128
#define TT 10
#define ROWS (BB*SS)

// scratch (static device globals: allocation-free)
__device__ float g_pre[ROWS * 16 + 128];  // [row][w*4+g] preactivation (+ pad for branchless prefetch)
__device__ float g_h[ROWS * 4];           // hidden states per (b,s), [row][w]

__device__ __forceinline__ float tanh_approx(float x) {
    float y;
    asm("tanh.approx.f32 %0, %1;" : "=f"(y) : "f"(x));
    return y;
}

// ---------------------------------------------------------------------------
// Kernel A: per-row projection. One thread per (row, wire w); computes all 4
// gates via float4-packed weights (1 LDS.128 + 4 FMA per k).
//   g_pre[row][w*4+g] = sum_k emb[x[row]][k]*Wg[k*4+w] + bg[w]+thg[w]
// ---------------------------------------------------------------------------
__global__ void pre_kernel(const int* __restrict__ x, const float* __restrict__ emb,
                           const float* __restrict__ Wf, const float* __restrict__ bf, const float* __restrict__ thf,
                           const float* __restrict__ Wi, const float* __restrict__ bi, const float* __restrict__ thi,
                           const float* __restrict__ Wu, const float* __restrict__ bu, const float* __restrict__ thu,
                           const float* __restrict__ Wo, const float* __restrict__ bo, const float* __restrict__ tho)
{
    __shared__ float4 sW4[128 * 4];  // sW4[k*4+w] = {Wf,Wi,Wu,Wo}[k*4+w]
    __shared__ float4 sC4[4];        // sC4[w] = {bf+thf, bi+thi, bu+thu, bo+tho}[w]

    int tid = threadIdx.x;
    // fill sW4: 2048 floats
    for (int idx = tid; idx < 128 * 4; idx += blockDim.x) {
        int k = idx >> 2, w = idx & 3;
        sW4[idx] = make_float4(Wf[k * 4 + w], Wi[k * 4 + w], Wu[k * 4 + w], Wo[k * 4 + w]);
    }
    if (tid < 4) {
        sC4[tid] = make_float4(bf[tid] + thf[tid], bi[tid] + thi[tid],
                               bu[tid] + thu[tid], bo[tid] + tho[tid]);
    }
    __syncthreads();

    int t = blockIdx.x * blockDim.x + tid;   // [0, ROWS*4)
    int w = t & 3;
    int row = t >> 2;
    const float4* e4 = (const float4*)(emb + (size_t)x[row] * EE);

    // 4 independent accumulator sets for ILP (one per c-slot), each float4 over gates
    float4 A0 = make_float4(0.f, 0.f, 0.f, 0.f);
    float4 A1 = A0, A2 = A0, A3 = A0;
    #pragma unroll
    for (int k4 = 0; k4 < 32; k4++) {
        float4 e = e4[k4];
        int k = k4 * 4;
        float4 w0 = sW4[(k + 0) * 4 + w];
        float4 w1 = sW4[(k + 1) * 4 + w];
        float4 w2 = sW4[(k + 2) * 4 + w];
        float4 w3 = sW4[(k + 3) * 4 + w];
        A0.x = fmaf(e.x, w0.x, A0.x); A0.y = fmaf(e.x, w0.y, A0.y);
        A0.z = fmaf(e.x, w0.z, A0.z); A0.w = fmaf(e.x, w0.w, A0.w);
        A1.x = fmaf(e.y, w1.x, A1.x); A1.y = fmaf(e.y, w1.y, A1.y);
        A1.z = fmaf(e.y, w1.z, A1.z); A1.w = fmaf(e.y, w1.w, A1.w);
        A2.x = fmaf(e.z, w2.x, A2.x); A2.y = fmaf(e.z, w2.y, A2.y);
        A2.z = fmaf(e.z, w2.z, A2.z); A2.w = fmaf(e.z, w2.w, A2.w);
        A3.x = fmaf(e.w, w3.x, A3.x); A3.y = fmaf(e.w, w3.y, A3.y);
        A3.z = fmaf(e.w, w3.z, A3.z); A3.w = fmaf(e.w, w3.w, A3.w);
    }
    float4 C = sC4[w];
    float4 r;
    r.x = (A0.x + A1.x) + (A2.x + A3.x) + C.x;
    r.y = (A0.y + A1.y) + (A2.y + A3.y) + C.y;
    r.z = (A0.z + A1.z) + (A2.z + A3.z) + C.z;
    r.w = (A0.w + A1.w) + (A2.w + A3.w) + C.w;
    // layout [row][w*4+g]: one coalesced float4 store per thread
    ((float4*)g_pre)[(size_t)row * 4 + w] = r;
}

// ---------------------------------------------------------------------------
// Kernel B: serial LSTM recurrence. ONE chain per warp (lanes 0-15 active,
// lane = g*4 + w), 64 warps. Linear branchless-prefetch reads of g_pre
// (lane offset w*4+g matches pre_kernel's store layout).
//   sigmoid(x) = 0.5*tanh(x/2)+0.5 ; g = tanh(q) ; h = o*tanh(c)
// ---------------------------------------------------------------------------
__global__ void __launch_bounds__(32, 1) rec_kernel(const float* __restrict__ Wf,
                                                    const float* __restrict__ Wi,
                                                    const float* __restrict__ Wu,
                                                    const float* __restrict__ Wo)
{
    const unsigned FULL = 0xffffffffu;
    int lane = threadIdx.x;
    int sub  = lane & 15;         // lane role (lanes 16-31 mirror 0-15, results unused)
    int g    = sub >> 2;          // gate: 0=f 1=i 2=u 3=o
    int w    = sub & 3;           // wire
    int b    = blockIdx.x;

    // this lane's 4 hidden-to-gate weights
    const float* Wg = (g == 0) ? Wf : (g == 1) ? Wi : (g == 2) ? Wu : Wo;
    float Wh0 = Wg[(128 + 0) * 4 + w];
    float Wh1 = Wg[(128 + 1) * 4 + w];
    float Wh2 = Wg[(128 + 2) * 4 + w];
    float Wh3 = Wg[(128 + 3) * 4 + w];

    // masked-product selectors for this wire's QLayer output
    const bool m0 = (w != 0);
    const bool m2 = (w == 0) | (w >= 2);
    const bool m3 = (w == 0) | (w == 3);
    // tanh arg scale: u-gate = tanh(q) ; sigmoids = tanh(q/2)
    const float tsc = (g == 2) ? 1.0f : 0.5f;
    const int gbase = sub & 12;

    const float* P = g_pre + (size_t)b * SS * 16 + (w * 4 + g);  // stride 16/step
    float* hout = g_h + (size_t)b * SS * 4 + w;                   // f-lanes store

    float hv = 0.f, cx = 0.f;

    // prefetch: current 4 steps + next 4 steps (padded array -> branchless)
    float pb0 = P[0 * 16], pb1 = P[1 * 16], pb2 = P[2 * 16], pb3 = P[3 * 16];

    for (int blk = 0; blk < 128; blk++) {
        float pc0 = pb0, pc1 = pb1, pc2 = pb2, pc3 = pb3;
        pb0 = P[4 * 16]; pb1 = P[5 * 16]; pb2 = P[6 * 16]; pb3 = P[7 * 16];
        P += 64;

        #pragma unroll
        for (int k = 0; k < 4; k++) {
            float p = (k == 0) ? pc0 : (k == 1) ? pc1 : (k == 2) ? pc2 : pc3;

            // broadcast hidden state (lives on f-lanes 0..3 of each segment)
            float hx0 = __shfl_sync(FULL, hv, 0, 16);
            float hx1 = __shfl_sync(FULL, hv, 1, 16);
            float hx2 = __shfl_sync(FULL, hv, 2, 16);
            float hx3 = __shfl_sync(FULL, hv, 3, 16);

            // this lane's angle and z
            float a = fmaf(hx1, Wh1, fmaf(hx0, Wh0, p)) + fmaf(hx3, Wh3, hx2 * Wh2);
            float z = __cosf(a);

            // gather z across the 4 wires of this gate group
            float z0 = __shfl_sync(FULL, z, gbase | 0, 16);
            float z1 = __shfl_sync(FULL, z, gbase | 1, 16);
            float z2 = __shfl_sync(FULL, z, gbase | 2, 16);
            float z3 = __shfl_sync(FULL, z, gbase | 3, 16);

            // masked product = QLayer output for (gate g, wire w)
            float t01 = (m0 ? z0 : 1.0f) * z1;
            float t23 = (m2 ? z2 : 1.0f) * (m3 ? z3 : 1.0f);
            float q = t01 * t23;

            // gate nonlinearity via MUFU.TANH
            float t = tanh_approx(q * tsc);

            // bring i, u, o tanh values to the f-lanes
            float ti = __shfl_sync(FULL, t, 4  | w, 16);
            float tu = __shfl_sync(FULL, t, 8  | w, 16);
            float to = __shfl_sync(FULL, t, 12 | w, 16);

            // cell + hidden update (meaningful on f-lanes only)
            float fv = fmaf(t,  0.5f, 0.5f);
            float iv = fmaf(ti, 0.5f, 0.5f);
            float ov = fmaf(to, 0.5f, 0.5f);
            float c  = fmaf(fv, cx, iv * tu);
            float hn = ov * tanh_approx(c);

            cx = c;
            hv = hn;
            if (g == 0 && lane < 16) hout[4 * k] = hn;
        }
        hout += 16;
    }
}

// ---------------------------------------------------------------------------
// Kernel C: logits [4 -> 10] + log_softmax. One thread per (b,s).
// ---------------------------------------------------------------------------
__global__ void out_kernel(const float* __restrict__ Wt, const float* __restrict__ bt,
                           float* __restrict__ out)
{
    __shared__ float sWt[4 * TT];
    __shared__ float sbt[TT];
    int tid = threadIdx.x;
    if (tid < 4 * TT) sWt[tid] = Wt[tid];
    if (tid < TT) sbt[tid] = bt[tid];
    __syncthreads();

    int row = blockIdx.x * blockDim.x + tid;
    if (row >= ROWS) return;
    float4 h = ((const float4*)g_h)[row];

    float lg[TT];
    #pragma unroll
    for (int t = 0; t < TT; t++) {
        float v = sbt[t];
        v = fmaf(h.x, sWt[0 * TT + t], v);
        v = fmaf(h.y, sWt[1 * TT + t], v);
        v = fmaf(h.z, sWt[2 * TT + t], v);
        v = fmaf(h.w, sWt[3 * TT + t], v);
        lg[t] = v;
    }
    float m = lg[0];
    #pragma unroll
    for (int t = 1; t < TT; t++) m = fmaxf(m, lg[t]);
    float sum = 0.f;
    #pragma unroll
    for (int t = 0; t < TT; t++) sum += __expf(lg[t] - m);
    float lse = m + __logf(sum);

    float2* o2 = (float2*)(out + (size_t)row * TT);
    #pragma unroll
    for (int t = 0; t < TT; t += 2)
        o2[t >> 1] = make_float2(lg[t] - lse, lg[t + 1] - lse);
}

// ---------------------------------------------------------------------------
extern "C" void kernel_launch(void* const* d_in, const int* in_sizes, int n_in,
                              void* d_out, int out_size)
{
    (void)in_sizes; (void)n_in; (void)out_size;
    const int*   x   = (const int*)  d_in[0];
    const float* emb = (const float*)d_in[1];
    const float* Wf  = (const float*)d_in[2];
    const float* bf  = (const float*)d_in[3];
    const float* thf = (const float*)d_in[4];
    const float* Wi  = (const float*)d_in[5];
    const float* bi  = (const float*)d_in[6];
    const float* thi = (const float*)d_in[7];
    const float* Wu  = (const float*)d_in[8];
    const float* bu  = (const float*)d_in[9];
    const float* thu = (const float*)d_in[10];
    const float* Wo  = (const float*)d_in[11];
    const float* bo  = (const float*)d_in[12];
    const float* tho = (const float*)d_in[13];
    const float* Wt  = (const float*)d_in[14];
    const float* bt  = (const float*)d_in[15];
    float* out = (float*)d_out;

    pre_kernel<<<(ROWS * 4) / 256, 256>>>(x, emb, Wf, bf, thf, Wi, bi, thi,
                                          Wu, bu, thu, Wo, bo, tho);
    rec_kernel<<<64, 32>>>(Wf, Wi, Wu, Wo);
    out_kernel<<<256, 128>>>(Wt, bt, out);
}